// round 12
// baseline (speedup 1.0000x reference)
#include <cuda_runtime.h>
#include <cuda_bf16.h>
#include <float.h>

// Problem shape (fixed by the dataset): Q=256, D=768, N=400000.
#define DDIM 768
#define MAXQ 256
#define MAXN 400000

// Scratch (allocations are banned -> __device__ globals)
__device__ float g_qn[MAXQ * DDIM];                      // L1-normalized queries
__device__ float g_sims[(size_t)MAXQ * (size_t)MAXN];    // full similarity matrix (~410MB)

// ---------------------------------------------------------------------------
// Kernel 1: L1-normalize each query row
// ---------------------------------------------------------------------------
__global__ void normq_kernel(const float* __restrict__ q, int Q) {
    int row = blockIdx.x;
    if (row >= Q) return;
    int tid = threadIdx.x;

    float s = 0.f;
    for (int d = tid; d < DDIM; d += 256)
        s += fabsf(q[(size_t)row * DDIM + d]);

    #pragma unroll
    for (int o = 16; o > 0; o >>= 1)
        s += __shfl_xor_sync(0xffffffffu, s, o);

    __shared__ float ws[8];
    __shared__ float inv;
    if ((tid & 31) == 0) ws[tid >> 5] = s;
    __syncthreads();
    if (tid == 0) {
        float t = 0.f;
        #pragma unroll
        for (int i = 0; i < 8; i++) t += ws[i];
        inv = 1.f / fmaxf(t, 1e-12f);
    }
    __syncthreads();

    float iv = inv;
    for (int d = tid; d < DDIM; d += 256)
        g_qn[(size_t)row * DDIM + d] = q[(size_t)row * DDIM + d] * iv;
}

// ---------------------------------------------------------------------------
// Kernel 2: fp32 GEMM  sims[Q,N] = qn[Q,D] @ emb[D,N]
// Tile 128x128, K-chunk 32, 256 threads, 8x8 microtile per thread.
// ---------------------------------------------------------------------------
__global__ __launch_bounds__(256, 2)
void sgemm_kernel(const float* __restrict__ B, int N, int Q) {
    __shared__ float As[32][128];   // [k][row]  (A transposed into smem)
    __shared__ float Bs[32][128];   // [k][col]

    const float* __restrict__ A = g_qn;
    float* __restrict__ C = g_sims;

    const int tid = threadIdx.x;
    const int tx  = tid & 15;       // 0..15 -> column groups
    const int ty  = tid >> 4;       // 0..15 -> row groups
    const int nBase = blockIdx.x * 128;
    const int qBase = blockIdx.y * 128;

    float acc[8][8];
    #pragma unroll
    for (int i = 0; i < 8; i++)
        #pragma unroll
        for (int j = 0; j < 8; j++) acc[i][j] = 0.f;

    float4 ldA[4], ldB[4];

    // ---- global load helpers (register staging) ----
    auto loadA = [&](int kBase) {
        #pragma unroll
        for (int it = 0; it < 4; ++it) {
            int idx = tid + it * 256;
            int row = idx >> 3;            // 0..127
            int k   = (idx & 7) * 4;       // 0..28
            int gr  = qBase + row;
            if (gr < Q)
                ldA[it] = *(const float4*)(A + (size_t)gr * DDIM + kBase + k);
            else
                ldA[it] = make_float4(0.f, 0.f, 0.f, 0.f);
        }
    };
    auto loadB = [&](int kBase) {
        #pragma unroll
        for (int it = 0; it < 4; ++it) {
            int idx = tid + it * 256;
            int kk  = idx >> 5;            // 0..31
            int n   = (idx & 31) * 4;      // 0..124
            int gn  = nBase + n;
            const float* src = B + (size_t)(kBase + kk) * N;
            if (gn + 3 < N) {
                ldB[it] = *(const float4*)(src + gn);
            } else {
                float4 v = make_float4(0.f, 0.f, 0.f, 0.f);
                if (gn + 0 < N) v.x = src[gn + 0];
                if (gn + 1 < N) v.y = src[gn + 1];
                if (gn + 2 < N) v.z = src[gn + 2];
                if (gn + 3 < N) v.w = src[gn + 3];
                ldB[it] = v;
            }
        }
    };
    auto storeTiles = [&]() {
        #pragma unroll
        for (int it = 0; it < 4; ++it) {
            int idx = tid + it * 256;
            int row = idx >> 3;
            int k   = (idx & 7) * 4;
            As[k + 0][row] = ldA[it].x;
            As[k + 1][row] = ldA[it].y;
            As[k + 2][row] = ldA[it].z;
            As[k + 3][row] = ldA[it].w;
        }
        #pragma unroll
        for (int it = 0; it < 4; ++it) {
            int idx = tid + it * 256;
            int kk  = idx >> 5;
            int n   = (idx & 31) * 4;
            *(float4*)&Bs[kk][n] = ldB[it];
        }
    };

    const int numK = DDIM / 32;   // 24
    loadA(0);
    loadB(0);

    for (int t = 0; t < numK; ++t) {
        storeTiles();
        __syncthreads();
        if (t + 1 < numK) {        // prefetch next K-chunk while computing
            loadA((t + 1) * 32);
            loadB((t + 1) * 32);
        }
        #pragma unroll
        for (int k = 0; k < 32; ++k) {
            float4 a0 = *(const float4*)&As[k][ty * 4];
            float4 a1 = *(const float4*)&As[k][64 + ty * 4];
            float4 b0 = *(const float4*)&Bs[k][tx * 4];
            float4 b1 = *(const float4*)&Bs[k][64 + tx * 4];
            float av[8] = {a0.x, a0.y, a0.z, a0.w, a1.x, a1.y, a1.z, a1.w};
            float bv[8] = {b0.x, b0.y, b0.z, b0.w, b1.x, b1.y, b1.z, b1.w};
            #pragma unroll
            for (int i = 0; i < 8; i++)
                #pragma unroll
                for (int j = 0; j < 8; j++)
                    acc[i][j] = fmaf(av[i], bv[j], acc[i][j]);
        }
        __syncthreads();
    }

    // ---- epilogue: store 8x8 microtile ----
    bool fullN = (nBase + 128 <= N);
    #pragma unroll
    for (int i = 0; i < 8; i++) {
        int lr = (i < 4) ? (ty * 4 + i) : (64 + ty * 4 + (i - 4));
        int gr = qBase + lr;
        if (gr >= Q) continue;
        float* dst = C + (size_t)gr * N + nBase;
        int c0 = tx * 4, c1 = 64 + tx * 4;
        if (fullN) {
            *(float4*)(dst + c0) = make_float4(acc[i][0], acc[i][1], acc[i][2], acc[i][3]);
            *(float4*)(dst + c1) = make_float4(acc[i][4], acc[i][5], acc[i][6], acc[i][7]);
        } else {
            #pragma unroll
            for (int j = 0; j < 8; j++) {
                int c = (j < 4) ? (c0 + j) : (c1 + (j - 4));
                if (nBase + c < N) dst[c] = acc[i][j];
            }
        }
    }
}

// ---------------------------------------------------------------------------
// Kernel 3: masked top-4 per query + output (values, then indices-as-float)
// Tie-break matches jax.lax.top_k: equal value -> lower index wins.
// ---------------------------------------------------------------------------
__global__ void topk_kernel(const int* __restrict__ startp, const int* __restrict__ endp,
                            float* __restrict__ out, int N, int Q) {
    int qrow = blockIdx.x;
    if (qrow >= Q) return;
    int tid = threadIdx.x;
    int start = startp[0];
    int end   = endp[0];

    const float* __restrict__ row = g_sims + (size_t)qrow * N;

    float bv[4] = {-FLT_MAX, -FLT_MAX, -FLT_MAX, -FLT_MAX};
    int   bi[4] = {0x7fffffff, 0x7fffffff, 0x7fffffff, 0x7fffffff};

    for (int n = tid; n < N; n += 256) {
        if (n >= start && n < end) continue;
        float v = row[n];
        if (v > bv[3]) {                       // strict > preserves lower-index-first
            bv[3] = v; bi[3] = n;
            if (bv[3] > bv[2]) { float tv = bv[2]; bv[2] = bv[3]; bv[3] = tv; int ti = bi[2]; bi[2] = bi[3]; bi[3] = ti;
            if (bv[2] > bv[1]) { tv = bv[1]; bv[1] = bv[2]; bv[2] = tv; ti = bi[1]; bi[1] = bi[2]; bi[2] = ti;
            if (bv[1] > bv[0]) { tv = bv[0]; bv[0] = bv[1]; bv[1] = tv; ti = bi[0]; bi[0] = bi[1]; bi[1] = ti; } } }
        }
    }

    __shared__ float sv[256 * 4];
    __shared__ int   si[256 * 4];
    #pragma unroll
    for (int j = 0; j < 4; j++) { sv[tid * 4 + j] = bv[j]; si[tid * 4 + j] = bi[j]; }
    __syncthreads();

    if (tid == 0) {
        float rv[4] = {-FLT_MAX, -FLT_MAX, -FLT_MAX, -FLT_MAX};
        int   ri[4] = {0x7fffffff, 0x7fffffff, 0x7fffffff, 0x7fffffff};
        for (int t = 0; t < 256 * 4; t++) {
            float v = sv[t]; int idx = si[t];
            if (v > rv[3] || (v == rv[3] && idx < ri[3])) {
                rv[3] = v; ri[3] = idx;
                #pragma unroll
                for (int p = 3; p > 0; p--) {
                    if (rv[p] > rv[p-1] || (rv[p] == rv[p-1] && ri[p] < ri[p-1])) {
                        float tv = rv[p-1]; rv[p-1] = rv[p]; rv[p] = tv;
                        int   ti = ri[p-1]; ri[p-1] = ri[p]; ri[p] = ti;
                    }
                }
            }
        }
        #pragma unroll
        for (int j = 0; j < 4; j++) {
            out[(size_t)qrow * 4 + j]                    = rv[j];          // values
            out[(size_t)Q * 4 + (size_t)qrow * 4 + j]    = (float)ri[j];   // indices
        }
    }
}

// ---------------------------------------------------------------------------
extern "C" void kernel_launch(void* const* d_in, const int* in_sizes, int n_in,
                              void* d_out, int out_size) {
    const float* query = (const float*)d_in[0];   // [Q, 768]
    const float* emb   = (const float*)d_in[1];   // [768, N]
    const int* startp  = (const int*)d_in[2];
    const int* endp    = (const int*)d_in[3];
    float* out = (float*)d_out;

    int Q = in_sizes[0] / DDIM;
    int N = in_sizes[1] / DDIM;
    if (Q <= 0 || N <= 0) return;
    if ((size_t)Q * (size_t)N > (size_t)MAXQ * (size_t)MAXN) return;  // scratch bound

    normq_kernel<<<Q, 256>>>(query, Q);

    dim3 grid((N + 127) / 128, (Q + 127) / 128);
    sgemm_kernel<<<grid, 256>>>(emb, N, Q);

    topk_kernel<<<Q, 256>>>(startp, endp, out, N, Q);
}

// round 13
// speedup vs baseline: 2.0556x; 2.0556x over previous
#include <cuda_runtime.h>
#include <cuda_bf16.h>
#include <float.h>
#include <limits.h>
#include <stdint.h>

// Problem shape (fixed by the dataset): Q=256, D=768, N=400000.
#define DDIM   768
#define MAXQ   256
#define MAXN   400000
#define NTILE  64
#define KCHUNK 32
#define CAND   16

// Scratch (allocations are banned -> __device__ globals)
__device__ float         g_qn  [MAXQ * DDIM];                  // L1-normalized queries (fp32)
__device__ __nv_bfloat16 g_qnb [MAXQ * DDIM];                  // bf16 copy for MMA
__device__ __nv_bfloat16 g_simsh[(size_t)MAXQ * (size_t)MAXN]; // bf16 similarity matrix (~205MB)

// ---------------------------------------------------------------------------
// Kernel 1: L1-normalize each query row -> fp32 + bf16; zero-pad rows >= Q
// ---------------------------------------------------------------------------
__global__ void normq_kernel(const float* __restrict__ q, int Q) {
    int row = blockIdx.x;
    int tid = threadIdx.x;

    if (row >= Q) {  // pad rows: zeros so GEMM M=256 tile is harmless
        for (int d = tid; d < DDIM; d += 256) {
            g_qn [(size_t)row * DDIM + d] = 0.f;
            g_qnb[(size_t)row * DDIM + d] = __float2bfloat16_rn(0.f);
        }
        return;
    }

    float s = 0.f;
    for (int d = tid; d < DDIM; d += 256)
        s += fabsf(q[(size_t)row * DDIM + d]);

    #pragma unroll
    for (int o = 16; o > 0; o >>= 1)
        s += __shfl_xor_sync(0xffffffffu, s, o);

    __shared__ float ws[8];
    __shared__ float inv;
    if ((tid & 31) == 0) ws[tid >> 5] = s;
    __syncthreads();
    if (tid == 0) {
        float t = 0.f;
        #pragma unroll
        for (int i = 0; i < 8; i++) t += ws[i];
        inv = 1.f / fmaxf(t, 1e-12f);
    }
    __syncthreads();

    float iv = inv;
    for (int d = tid; d < DDIM; d += 256) {
        float v = q[(size_t)row * DDIM + d] * iv;
        g_qn [(size_t)row * DDIM + d] = v;
        g_qnb[(size_t)row * DDIM + d] = __float2bfloat16_rn(v);
    }
}

// ---------------------------------------------------------------------------
// Kernel 2: bf16 tensor-core GEMM  sims[256,N] = qnb[256,768] @ bf16(emb[768,N])
// Tile: M=256 (whole query set), N=64 per CTA, K-chunk 32.
// 256 threads = 8 warps laid out 4(M) x 2(N); warp tile 64x32 via m16n8k16 mma.
// emb (fp32) is converted to bf16 on load; read from DRAM exactly once.
// ---------------------------------------------------------------------------
__global__ __launch_bounds__(256)
void gemm_bf16_kernel(const float* __restrict__ B, int N, int Q) {
    // Pads chosen so ldmatrix 16B rows are 16B-aligned AND conflict-free:
    // As row stride 40 elems = 80B (bank inc 20), Bs row stride 72 elems = 144B (bank inc 4).
    __shared__ __nv_bfloat16 As[MAXQ][40];    // [m][k]  20KB
    __shared__ __nv_bfloat16 Bs[KCHUNK][72];  // [k][n]  4.5KB

    const int tid  = threadIdx.x;
    const int lane = tid & 31;
    const int wid  = tid >> 5;     // 0..7
    const int wm   = wid & 3;      // M block (64 rows)
    const int wn   = wid >> 2;     // N block (32 cols)
    const int nBase = blockIdx.x * NTILE;

    float acc[4][4][4];
    #pragma unroll
    for (int i = 0; i < 4; i++)
        #pragma unroll
        for (int j = 0; j < 4; j++)
            #pragma unroll
            for (int r = 0; r < 4; r++) acc[i][j][r] = 0.f;

    uint4  stA[4];
    float4 stB[2];

    auto loadA = [&](int kBase) {
        #pragma unroll
        for (int p = 0; p < 4; ++p) {
            int m = p * 64 + (tid >> 2);
            int k = (tid & 3) * 8;
            stA[p] = *(const uint4*)(g_qnb + (size_t)m * DDIM + kBase + k);
        }
    };
    auto loadB = [&](int kBase) {
        int k = tid >> 3;                       // 0..31
        int n = nBase + (tid & 7) * 8;          // 8 floats per thread
        const float* src = B + (size_t)(kBase + k) * N;
        if (n + 7 < N) {
            stB[0] = *(const float4*)(src + n);
            stB[1] = *(const float4*)(src + n + 4);
        } else {
            float t[8];
            #pragma unroll
            for (int j = 0; j < 8; j++) t[j] = (n + j < N) ? src[n + j] : 0.f;
            stB[0] = make_float4(t[0], t[1], t[2], t[3]);
            stB[1] = make_float4(t[4], t[5], t[6], t[7]);
        }
    };
    auto storeTiles = [&]() {
        #pragma unroll
        for (int p = 0; p < 4; ++p) {
            int m = p * 64 + (tid >> 2);
            int k = (tid & 3) * 8;
            *(uint4*)(&As[m][k]) = stA[p];
        }
        int k = tid >> 3;
        int n = (tid & 7) * 8;
        __nv_bfloat162 b2[4];
        b2[0] = __floats2bfloat162_rn(stB[0].x, stB[0].y);
        b2[1] = __floats2bfloat162_rn(stB[0].z, stB[0].w);
        b2[2] = __floats2bfloat162_rn(stB[1].x, stB[1].y);
        b2[3] = __floats2bfloat162_rn(stB[1].z, stB[1].w);
        *(uint4*)(&Bs[k][n]) = *(uint4*)b2;
    };

    const int numK = DDIM / KCHUNK;  // 24
    loadA(0);
    loadB(0);

    for (int t = 0; t < numK; ++t) {
        __syncthreads();
        storeTiles();
        __syncthreads();
        if (t + 1 < numK) {             // global prefetch (register staged)
            loadA((t + 1) * KCHUNK);
            loadB((t + 1) * KCHUNK);
        }

        #pragma unroll
        for (int ks = 0; ks < 2; ++ks) {          // two k16 steps per chunk
            uint32_t a[4][4];
            uint32_t b[4][2];
            #pragma unroll
            for (int mi = 0; mi < 4; ++mi) {
                const __nv_bfloat16* p =
                    &As[wm * 64 + mi * 16 + (lane & 15)][ks * 16 + (lane >> 4) * 8];
                uint32_t addr = (uint32_t)__cvta_generic_to_shared(p);
                asm volatile(
                    "ldmatrix.sync.aligned.m8n8.x4.shared.b16 {%0,%1,%2,%3}, [%4];"
                    : "=r"(a[mi][0]), "=r"(a[mi][1]), "=r"(a[mi][2]), "=r"(a[mi][3])
                    : "r"(addr));
            }
            #pragma unroll
            for (int ni = 0; ni < 4; ++ni) {
                const __nv_bfloat16* p =
                    &Bs[ks * 16 + (lane & 15)][wn * 32 + ni * 8];
                uint32_t addr = (uint32_t)__cvta_generic_to_shared(p);
                asm volatile(
                    "ldmatrix.sync.aligned.m8n8.x2.trans.shared.b16 {%0,%1}, [%2];"
                    : "=r"(b[ni][0]), "=r"(b[ni][1])
                    : "r"(addr));
            }
            #pragma unroll
            for (int mi = 0; mi < 4; ++mi)
                #pragma unroll
                for (int ni = 0; ni < 4; ++ni)
                    asm volatile(
                        "mma.sync.aligned.m16n8k16.row.col.f32.bf16.bf16.f32 "
                        "{%0,%1,%2,%3}, {%4,%5,%6,%7}, {%8,%9}, {%0,%1,%2,%3};"
                        : "+f"(acc[mi][ni][0]), "+f"(acc[mi][ni][1]),
                          "+f"(acc[mi][ni][2]), "+f"(acc[mi][ni][3])
                        : "r"(a[mi][0]), "r"(a[mi][1]), "r"(a[mi][2]), "r"(a[mi][3]),
                          "r"(b[ni][0]), "r"(b[ni][1]));
        }
    }

    // ---- epilogue: fp32 acc -> bf16 sims ----
    #pragma unroll
    for (int mi = 0; mi < 4; ++mi) {
        int m0 = wm * 64 + mi * 16 + (lane >> 2);   // rows m0 and m0+8
        #pragma unroll
        for (int ni = 0; ni < 4; ++ni) {
            int n = nBase + wn * 32 + ni * 8 + (lane & 3) * 2;
            __nv_bfloat162 v01 = __floats2bfloat162_rn(acc[mi][ni][0], acc[mi][ni][1]);
            __nv_bfloat162 v23 = __floats2bfloat162_rn(acc[mi][ni][2], acc[mi][ni][3]);
            if (n + 1 < N) {
                if (((N & 1) == 0)) {  // 4B-aligned path (N even)
                    *(__nv_bfloat162*)(g_simsh + (size_t)m0 * N + n)       = v01;
                    *(__nv_bfloat162*)(g_simsh + (size_t)(m0 + 8) * N + n) = v23;
                } else {
                    g_simsh[(size_t)m0 * N + n]           = v01.x;
                    g_simsh[(size_t)m0 * N + n + 1]       = v01.y;
                    g_simsh[(size_t)(m0 + 8) * N + n]     = v23.x;
                    g_simsh[(size_t)(m0 + 8) * N + n + 1] = v23.y;
                }
            } else if (n < N) {
                g_simsh[(size_t)m0 * N + n]       = v01.x;
                g_simsh[(size_t)(m0 + 8) * N + n] = v23.x;
            }
        }
    }
}

// ---------------------------------------------------------------------------
// Kernel 3: masked top-16 candidates from bf16 sims, exact fp32 rescore, top-4.
// Tie-break matches jax.lax.top_k: equal value -> lower index wins.
// ---------------------------------------------------------------------------
__global__ void topk_rescore_kernel(const float* __restrict__ emb,
                                    const int* __restrict__ startp,
                                    const int* __restrict__ endp,
                                    float* __restrict__ out, int N, int Q) {
    int q = blockIdx.x;
    if (q >= Q) return;
    int tid = threadIdx.x;
    int start = startp[0];
    int end   = endp[0];

    const __nv_bfloat16* __restrict__ row = g_simsh + (size_t)q * N;

    // --- per-thread top-4 over bf16 sims (strict > keeps lowest index) ---
    float bv[4] = {-FLT_MAX, -FLT_MAX, -FLT_MAX, -FLT_MAX};
    int   bi[4] = {INT_MAX, INT_MAX, INT_MAX, INT_MAX};
    for (int n = tid; n < N; n += 256) {
        if (n >= start && n < end) continue;
        float v = __bfloat162float(row[n]);
        if (v > bv[3]) {
            bv[3] = v; bi[3] = n;
            #pragma unroll
            for (int p = 3; p > 0; p--) {
                if (bv[p] > bv[p-1]) {
                    float tv = bv[p-1]; bv[p-1] = bv[p]; bv[p] = tv;
                    int   ti = bi[p-1]; bi[p-1] = bi[p]; bi[p] = ti;
                }
            }
        }
    }

    __shared__ float sv[256 * 4];
    __shared__ int   si[256 * 4];
    #pragma unroll
    for (int j = 0; j < 4; j++) { sv[tid * 4 + j] = bv[j]; si[tid * 4 + j] = bi[j]; }
    __syncthreads();

    // --- thread 0: merge 1024 -> top-16 candidates ---
    __shared__ int   candIdx[CAND];
    __shared__ float candVal[CAND];
    if (tid == 0) {
        float rv[CAND]; int ri[CAND];
        #pragma unroll
        for (int i = 0; i < CAND; i++) { rv[i] = -FLT_MAX; ri[i] = INT_MAX; }
        for (int t = 0; t < 256 * 4; t++) {
            float v = sv[t]; int idx = si[t];
            if (idx == INT_MAX) continue;
            if (v > rv[CAND-1] || (v == rv[CAND-1] && idx < ri[CAND-1])) {
                rv[CAND-1] = v; ri[CAND-1] = idx;
                #pragma unroll
                for (int p = CAND-1; p > 0; p--) {
                    if (rv[p] > rv[p-1] || (rv[p] == rv[p-1] && ri[p] < ri[p-1])) {
                        float tv = rv[p-1]; rv[p-1] = rv[p]; rv[p] = tv;
                        int   ti = ri[p-1]; ri[p-1] = ri[p]; ri[p] = ti;
                    }
                }
            }
        }
        #pragma unroll
        for (int i = 0; i < CAND; i++) candIdx[i] = ri[i];
    }
    __syncthreads();

    // --- exact fp32 rescore: 16 candidates x 16 lanes each ---
    int c = tid >> 4;          // candidate 0..15
    int l = tid & 15;          // lane in half-warp (aligned to warp halves)
    int idx = candIdx[c];
    float s = 0.f;
    if (idx >= 0 && idx < N) {
        const float* __restrict__ qrow = g_qn + (size_t)q * DDIM;
        for (int d = l; d < DDIM; d += 16)
            s += qrow[d] * emb[(size_t)d * N + idx];
    }
    #pragma unroll
    for (int o = 8; o > 0; o >>= 1)
        s += __shfl_down_sync(0xffffffffu, s, o, 16);
    if (l == 0) candVal[c] = (idx >= 0 && idx < N) ? s : -FLT_MAX;
    __syncthreads();

    // --- thread 0: top-4 of exact values, write output ---
    if (tid == 0) {
        float fv[4] = {-FLT_MAX, -FLT_MAX, -FLT_MAX, -FLT_MAX};
        int   fi[4] = {INT_MAX, INT_MAX, INT_MAX, INT_MAX};
        for (int cc = 0; cc < CAND; cc++) {
            float v = candVal[cc]; int ix = candIdx[cc];
            if (ix == INT_MAX) continue;
            if (v > fv[3] || (v == fv[3] && ix < fi[3])) {
                fv[3] = v; fi[3] = ix;
                #pragma unroll
                for (int p = 3; p > 0; p--) {
                    if (fv[p] > fv[p-1] || (fv[p] == fv[p-1] && fi[p] < fi[p-1])) {
                        float tv = fv[p-1]; fv[p-1] = fv[p]; fv[p] = tv;
                        int   ti = fi[p-1]; fi[p-1] = fi[p]; fi[p] = ti;
                    }
                }
            }
        }
        #pragma unroll
        for (int j = 0; j < 4; j++) {
            out[(size_t)q * 4 + j]                 = fv[j];         // values
            out[(size_t)Q * 4 + (size_t)q * 4 + j] = (float)fi[j];  // indices
        }
    }
}

// ---------------------------------------------------------------------------
extern "C" void kernel_launch(void* const* d_in, const int* in_sizes, int n_in,
                              void* d_out, int out_size) {
    const float* query = (const float*)d_in[0];   // [Q, 768]
    const float* emb   = (const float*)d_in[1];   // [768, N]
    const int* startp  = (const int*)d_in[2];
    const int* endp    = (const int*)d_in[3];
    float* out = (float*)d_out;

    int Q = in_sizes[0] / DDIM;
    int N = in_sizes[1] / DDIM;
    if (Q <= 0 || N <= 0) return;
    if (Q > MAXQ || N > MAXN) return;   // scratch bound

    normq_kernel<<<MAXQ, 256>>>(query, Q);

    int gridN = (N + NTILE - 1) / NTILE;
    gemm_bf16_kernel<<<gridN, 256>>>(emb, N, Q);

    topk_rescore_kernel<<<Q, 256>>>(emb, startp, endp, out, N, Q);
}